// round 1
// baseline (speedup 1.0000x reference)
#include <cuda_runtime.h>
#include <cstdint>

// InferenceEmbeddingTable: hash-bucket lookup + embedding row gather.
// Inputs (metadata order):
//  0 indices              int32 [N]                (N = 524288)
//  1 offsets              int32 [F+1]              (feature segment offsets)
//  2 bucket_keys          int32 [total_buckets*128]
//  3 table_offsets        int32 [F+1]              (row offsets into emb memory)
//  4 table_bucket_offsets int32 [F+1]
//  5 num_buckets          int32 [F]
//  6 emb_table            fp32  [total_rows*128]
// Output: fp32 [N*128]
//
// One warp per index:
//   lane l reads int4 #l of the 512B bucket row (coalesced LDG.128),
//   ballot+ffs -> first matching slot (== argmax of match),
//   lane l reads float4 #l of the 512B embedding row, writes float4 #l of out.

#define BUCKET_CAP 128
#define EMB_DIM    128

__global__ __launch_bounds__(256)
void emb_lookup_kernel(const int* __restrict__ indices,
                       const int* __restrict__ offsets,
                       const int4* __restrict__ bucket_keys,   // [total_buckets*32]
                       const int* __restrict__ table_offsets,
                       const int* __restrict__ table_bucket_offsets,
                       const int* __restrict__ num_buckets,
                       const float4* __restrict__ emb,         // [total_rows*32]
                       float4* __restrict__ out,               // [N*32]
                       int N, int num_features)
{
    const int gtid = blockIdx.x * blockDim.x + threadIdx.x;
    const int warp = gtid >> 5;
    const int lane = threadIdx.x & 31;
    if (warp >= N) return;

    const int key = __ldg(&indices[warp]);

    // searchsorted(offsets, i, 'right') - 1  (offsets[0] == 0)
    int tid = 0;
    #pragma unroll 8
    for (int f = 1; f < num_features; ++f)
        tid += (warp >= __ldg(&offsets[f]));

    const int nb       = __ldg(&num_buckets[tid]);
    const int b_local  = key % nb;                         // hash bucket in table
    const int b_global = __ldg(&table_bucket_offsets[tid]) + b_local;

    // Probe: 128 slots = 32 x int4, one per lane (coalesced 512B, L2-resident).
    const int4 k4 = __ldg(&bucket_keys[(long)b_global * 32 + lane]);
    int m = (k4.x == key ? 1 : 0) | (k4.y == key ? 2 : 0)
          | (k4.z == key ? 4 : 0) | (k4.w == key ? 8 : 0);
    const unsigned ball = __ballot_sync(0xffffffffu, m != 0);

    float4 v = make_float4(0.f, 0.f, 0.f, 0.f);
    if (ball) {
        const int src_lane = __ffs(ball) - 1;              // first lane with a match
        const int mm       = __shfl_sync(0xffffffffu, m, src_lane);
        const int slot     = src_lane * 4 + (__ffs(mm) - 1); // first matching slot
        const int row      = __ldg(&table_offsets[tid]) + b_local * BUCKET_CAP + slot;
        v = __ldg(&emb[(long)row * 32 + lane]);            // coalesced 512B gather
    }
    out[(long)warp * 32 + lane] = v;                        // coalesced 512B store
}

extern "C" void kernel_launch(void* const* d_in, const int* in_sizes, int n_in,
                              void* d_out, int out_size)
{
    const int*    indices              = (const int*)   d_in[0];
    const int*    offsets              = (const int*)   d_in[1];
    const int4*   bucket_keys          = (const int4*)  d_in[2];
    const int*    table_offsets        = (const int*)   d_in[3];
    const int*    table_bucket_offsets = (const int*)   d_in[4];
    const int*    num_buckets          = (const int*)   d_in[5];
    const float4* emb                  = (const float4*)d_in[6];
    float4*       out                  = (float4*)      d_out;

    const int N            = in_sizes[0];
    const int num_features = in_sizes[5];          // == len(num_buckets)

    const int threads = 256;                        // 8 warps / block
    const long total_threads = (long)N * 32;
    const int blocks = (int)((total_threads + threads - 1) / threads);

    emb_lookup_kernel<<<blocks, threads>>>(indices, offsets, bucket_keys,
                                           table_offsets, table_bucket_offsets,
                                           num_buckets, emb, out,
                                           N, num_features);
}

// round 3
// speedup vs baseline: 1.3797x; 1.3797x over previous
#include <cuda_runtime.h>
#include <cstdint>

// InferenceEmbeddingTable: hash-bucket lookup + embedding row gather.
// R2: 4 indices per warp (MLP=4 per memory stage), pow2 fast-path for the
// bucket hash, streaming cache hints on emb gather + output store.

#define BUCKET_CAP 128
#define IPW 4                      // indices per warp

__global__ __launch_bounds__(256)
void emb_lookup_kernel(const int* __restrict__ indices,
                       const int* __restrict__ offsets,
                       const int4* __restrict__ bucket_keys,   // [total_buckets*32]
                       const int* __restrict__ table_offsets,
                       const int* __restrict__ table_bucket_offsets,
                       const int* __restrict__ num_buckets,
                       const float4* __restrict__ emb,         // [total_rows*32]
                       float4* __restrict__ out,               // [N*32]
                       int N, int num_features)
{
    const int gtid = blockIdx.x * blockDim.x + threadIdx.x;
    const int warp = gtid >> 5;
    const int lane = threadIdx.x & 31;
    const int base = warp * IPW;
    if (base >= N) return;

    // 4 keys, uniform 16B load (broadcast across warp).
    const int4 keys4 = __ldg((const int4*)&indices[base]);
    int keys[IPW] = {keys4.x, keys4.y, keys4.z, keys4.w};

    // Stage 1: resolve table + bucket per index, issue all 4 probe loads.
    int4 k4[IPW];
    int  bl[IPW], tid[IPW];
    #pragma unroll
    for (int j = 0; j < IPW; ++j) {
        const int pos = base + j;
        int t = 0;
        #pragma unroll 8
        for (int f = 1; f < num_features; ++f)
            t += (pos >= __ldg(&offsets[f]));
        tid[j] = t;
        const unsigned nb = (unsigned)__ldg(&num_buckets[t]);
        unsigned b;
        if ((nb & (nb - 1u)) == 0u) b = (unsigned)keys[j] & (nb - 1u);  // pow2 fast path
        else                        b = (unsigned)keys[j] % nb;
        bl[j] = (int)b;
        const int b_global = __ldg(&table_bucket_offsets[t]) + (int)b;
        k4[j] = __ldg(&bucket_keys[(long)b_global * 32 + lane]);        // L2-resident probe
    }

    // Stage 2: match + first-slot, issue all 4 emb gathers.
    float4 v[IPW];
    #pragma unroll
    for (int j = 0; j < IPW; ++j) {
        const int key = keys[j];
        int m = (k4[j].x == key ? 1 : 0) | (k4[j].y == key ? 2 : 0)
              | (k4[j].z == key ? 4 : 0) | (k4[j].w == key ? 8 : 0);
        const unsigned ball = __ballot_sync(0xffffffffu, m != 0);
        v[j] = make_float4(0.f, 0.f, 0.f, 0.f);
        if (ball) {
            const int src  = __ffs(ball) - 1;
            const int mm   = __shfl_sync(0xffffffffu, m, src);
            const int slot = src * 4 + (__ffs(mm) - 1);
            const int row  = __ldg(&table_offsets[tid[j]]) + bl[j] * BUCKET_CAP + slot;
            v[j] = __ldcs(&emb[(long)row * 32 + lane]);   // streaming: no-reuse 1GB table
        }
    }

    // Stage 3: 4 coalesced 512B stores (streaming).
    #pragma unroll
    for (int j = 0; j < IPW; ++j) {
        const int pos = base + j;
        if (pos < N) __stcs(&out[(long)pos * 32 + lane], v[j]);
    }
}

extern "C" void kernel_launch(void* const* d_in, const int* in_sizes, int n_in,
                              void* d_out, int out_size)
{
    const int*    indices              = (const int*)   d_in[0];
    const int*    offsets              = (const int*)   d_in[1];
    const int4*   bucket_keys          = (const int4*)  d_in[2];
    const int*    table_offsets        = (const int*)   d_in[3];
    const int*    table_bucket_offsets = (const int*)   d_in[4];
    const int*    num_buckets          = (const int*)   d_in[5];
    const float4* emb                  = (const float4*)d_in[6];
    float4*       out                  = (float4*)      d_out;

    const int N            = in_sizes[0];
    const int num_features = in_sizes[5];

    const int threads = 256;                         // 8 warps * 4 idx = 32 idx/block
    const int idx_per_block = (threads / 32) * IPW;
    const int blocks = (N + idx_per_block - 1) / idx_per_block;

    emb_lookup_kernel<<<blocks, threads>>>(indices, offsets, bucket_keys,
                                           table_offsets, table_bucket_offsets,
                                           num_buckets, emb, out,
                                           N, num_features);
}

// round 5
// speedup vs baseline: 1.4258x; 1.0334x over previous
#include <cuda_runtime.h>
#include <cstdint>

// InferenceEmbeddingTable: hash-bucket lookup + embedding row gather.
// R3: IPW=4 MLP structure kept; metadata hoisted to registers, redux-min slot
// select (replaces ballot+shfl+ffs), pure 32-bit index math, streaming hints.

#define BUCKET_CAP 128
#define IPW 4                      // indices per warp
#define MAXF 8                     // max features supported in fast path

__global__ __launch_bounds__(256)
void emb_lookup_kernel(const int* __restrict__ indices,
                       const int* __restrict__ offsets,
                       const int4* __restrict__ bucket_keys,   // [total_buckets*32]
                       const int* __restrict__ table_offsets,
                       const int* __restrict__ table_bucket_offsets,
                       const int* __restrict__ num_buckets,
                       const float4* __restrict__ emb,         // [total_rows*32]
                       float4* __restrict__ out,               // [N*32]
                       int N, int num_features)
{
    const int gtid = blockIdx.x * blockDim.x + threadIdx.x;
    const int warp = gtid >> 5;
    const int lane = threadIdx.x & 31;
    const int base = warp * IPW;
    if (base >= N) return;

    // Hoist segment boundaries (uniform, tiny, L1-resident) into registers.
    int offs[MAXF - 1];
    #pragma unroll
    for (int f = 0; f < MAXF - 1; ++f)
        offs[f] = (f + 1 < num_features) ? __ldg(&offsets[f + 1]) : 0x7fffffff;

    // 4 keys via one uniform 16B load.
    const int4 keys4 = __ldg((const int4*)&indices[base]);
    const int keys[IPW] = {keys4.x, keys4.y, keys4.z, keys4.w};

    // Stage 1: resolve table + bucket per index, issue all 4 probe loads.
    int4 k4[IPW];
    int  bl[IPW], tid[IPW];
    #pragma unroll
    for (int j = 0; j < IPW; ++j) {
        const int pos = base + j;
        int t = 0;
        #pragma unroll
        for (int f = 0; f < MAXF - 1; ++f)
            t += (pos >= offs[f]);
        tid[j] = t;
        const unsigned nb = (unsigned)__ldg(&num_buckets[t]);
        unsigned b;
        if ((nb & (nb - 1u)) == 0u) b = (unsigned)keys[j] & (nb - 1u);  // pow2 fast path
        else                        b = (unsigned)keys[j] % nb;
        bl[j] = (int)b;
        const int b_global = __ldg(&table_bucket_offsets[t]) + (int)b;
        k4[j] = __ldg(&bucket_keys[b_global * 32 + lane]);      // L2-resident probe
    }

    // Stage 2: first-match slot via redux-min (lane order == slot order),
    // then issue all 4 emb gathers.
    float4 v[IPW];
    #pragma unroll
    for (int j = 0; j < IPW; ++j) {
        const int key = keys[j];
        const int m = (k4[j].x == key ? 1 : 0) | (k4[j].y == key ? 2 : 0)
                    | (k4[j].z == key ? 4 : 0) | (k4[j].w == key ? 8 : 0);
        const int cand = m ? (lane * 4 + (__ffs(m) - 1)) : 0x7fffffff;
        const int slot = __reduce_min_sync(0xffffffffu, cand);
        v[j] = make_float4(0.f, 0.f, 0.f, 0.f);
        if (slot < BUCKET_CAP) {
            const int row = __ldg(&table_offsets[tid[j]]) + bl[j] * BUCKET_CAP + slot;
            v[j] = __ldcs(&emb[row * 32 + lane]);               // streaming, no reuse
        }
    }

    // Stage 3: 4 coalesced 512B streaming stores.
    #pragma unroll
    for (int j = 0; j < IPW; ++j) {
        const int pos = base + j;
        if (pos < N) __stcs(&out[pos * 32 + lane], v[j]);
    }
}

extern "C" void kernel_launch(void* const* d_in, const int* in_sizes, int n_in,
                              void* d_out, int out_size)
{
    const int*    indices              = (const int*)   d_in[0];
    const int*    offsets              = (const int*)   d_in[1];
    const int4*   bucket_keys          = (const int4*)  d_in[2];
    const int*    table_offsets        = (const int*)   d_in[3];
    const int*    table_bucket_offsets = (const int*)   d_in[4];
    const int*    num_buckets          = (const int*)   d_in[5];
    const float4* emb                  = (const float4*)d_in[6];
    float4*       out                  = (float4*)      d_out;

    const int N            = in_sizes[0];
    const int num_features = in_sizes[5];

    const int threads = 256;                         // 8 warps * 4 idx = 32 idx/block
    const int idx_per_block = (threads / 32) * IPW;
    const int blocks = (N + idx_per_block - 1) / idx_per_block;

    emb_lookup_kernel<<<blocks, threads>>>(indices, offsets, bucket_keys,
                                           table_offsets, table_bucket_offsets,
                                           num_buckets, emb, out,
                                           N, num_features);
}

// round 6
// speedup vs baseline: 1.4419x; 1.0113x over previous
#include <cuda_runtime.h>
#include <cstdint>

// InferenceEmbeddingTable: hash-bucket lookup + embedding row gather.
// R4: speculative slot prediction. Bucket layout stores key k at slot k/nb,
// so we predict the slot, verify with ONE 4-byte key load (overlapped with the
// speculative 512B emb gather), and only fall back to the full 128-slot probe
// on mismatch (correct for arbitrary data / missing keys).

#define BUCKET_CAP 128
#define IPW 4                      // indices per warp
#define MAXF 8                     // max features in fast path

__global__ __launch_bounds__(256)
void emb_lookup_kernel(const int* __restrict__ indices,
                       const int* __restrict__ offsets,
                       const int* __restrict__ bucket_keys,    // [total_buckets*128]
                       const int* __restrict__ table_offsets,
                       const int* __restrict__ table_bucket_offsets,
                       const int* __restrict__ num_buckets,
                       const float4* __restrict__ emb,         // [total_rows*32]
                       float4* __restrict__ out,               // [N*32]
                       int N, int num_features)
{
    const int gtid = blockIdx.x * blockDim.x + threadIdx.x;
    const int warp = gtid >> 5;
    const int lane = threadIdx.x & 31;
    const int base = warp * IPW;
    if (base >= N) return;

    // Hoisted segment boundaries (uniform, L1-resident).
    int offs[MAXF - 1];
    #pragma unroll
    for (int f = 0; f < MAXF - 1; ++f)
        offs[f] = (f + 1 < num_features) ? __ldg(&offsets[f + 1]) : 0x7fffffff;

    const int4 keys4 = __ldg((const int4*)&indices[base]);
    const int keys[IPW] = {keys4.x, keys4.y, keys4.z, keys4.w};

    // Per-index metadata (uniform across warp): table, bucket, predicted slot.
    int tidj[IPW], blj[IPW], gsj[IPW], bgj[IPW], rowj[IPW];
    bool validj[IPW];
    #pragma unroll
    for (int j = 0; j < IPW; ++j) {
        const int pos = base + j;
        int t = 0;
        #pragma unroll
        for (int f = 0; f < MAXF - 1; ++f)
            t += (pos >= offs[f]);
        tidj[j] = t;
        const unsigned nb = (unsigned)__ldg(&num_buckets[t]);
        const unsigned key = (unsigned)keys[j];
        unsigned b, gs;
        if ((nb & (nb - 1u)) == 0u) {                 // pow2 fast path
            b  = key & (nb - 1u);
            gs = key >> __popc(nb - 1u);
        } else {
            b  = key % nb;
            gs = key / nb;
        }
        blj[j]    = (int)b;
        validj[j] = (gs < BUCKET_CAP);
        gsj[j]    = validj[j] ? (int)gs : 0;
        bgj[j]    = __ldg(&table_bucket_offsets[t]) + (int)b;
        rowj[j]   = __ldg(&table_offsets[t]) + (int)b * BUCKET_CAP + gsj[j];
    }

    // Speculative emb gathers FIRST (DRAM, long latency) — 4 in flight.
    float4 v[IPW];
    #pragma unroll
    for (int j = 0; j < IPW; ++j)
        v[j] = __ldcs(&emb[rowj[j] * 32 + lane]);

    // Verification loads: lane j checks index j's predicted slot (L2 hit),
    // fully overlapped with the gathers above.
    int chk = 0x80000000;
    if (lane < IPW) {
        const int mybg = (lane == 0) ? bgj[0] : (lane == 1) ? bgj[1]
                       : (lane == 2) ? bgj[2] : bgj[3];
        const int mygs = (lane == 0) ? gsj[0] : (lane == 1) ? gsj[1]
                       : (lane == 2) ? gsj[2] : gsj[3];
        chk = __ldg(&bucket_keys[mybg * BUCKET_CAP + mygs]);
    }
    const int mykey = (lane == 0) ? keys[0] : (lane == 1) ? keys[1]
                    : (lane == 2) ? keys[2] : keys[3];
    const bool myvalid = (lane == 0) ? validj[0] : (lane == 1) ? validj[1]
                       : (lane == 2) ? validj[2] : validj[3];
    const unsigned okm = __ballot_sync(0xffffffffu,
                                       (lane < IPW) && myvalid && (chk == mykey));

    // Commit: fast path stores the speculative row; slow path does the full
    // 128-slot probe (handles arbitrary placement and missing keys).
    #pragma unroll
    for (int j = 0; j < IPW; ++j) {
        const int pos = base + j;
        if (pos >= N) break;
        if ((okm >> j) & 1u) {
            __stcs(&out[pos * 32 + lane], v[j]);
        } else {
            const int key = keys[j];
            const int4 kk = __ldg((const int4*)bucket_keys + bgj[j] * 32 + lane);
            const int m = (kk.x == key ? 1 : 0) | (kk.y == key ? 2 : 0)
                        | (kk.z == key ? 4 : 0) | (kk.w == key ? 8 : 0);
            const int cand = m ? (lane * 4 + (__ffs(m) - 1)) : 0x7fffffff;
            const int slot = __reduce_min_sync(0xffffffffu, cand);
            float4 r = make_float4(0.f, 0.f, 0.f, 0.f);
            if (slot < BUCKET_CAP) {
                const int row = __ldg(&table_offsets[tidj[j]])
                              + blj[j] * BUCKET_CAP + slot;
                r = __ldcs(&emb[row * 32 + lane]);
            }
            __stcs(&out[pos * 32 + lane], r);
        }
    }
}

extern "C" void kernel_launch(void* const* d_in, const int* in_sizes, int n_in,
                              void* d_out, int out_size)
{
    const int*    indices              = (const int*)   d_in[0];
    const int*    offsets              = (const int*)   d_in[1];
    const int*    bucket_keys          = (const int*)   d_in[2];
    const int*    table_offsets        = (const int*)   d_in[3];
    const int*    table_bucket_offsets = (const int*)   d_in[4];
    const int*    num_buckets          = (const int*)   d_in[5];
    const float4* emb                  = (const float4*)d_in[6];
    float4*       out                  = (float4*)      d_out;

    const int N            = in_sizes[0];
    const int num_features = in_sizes[5];

    const int threads = 256;                         // 8 warps * 4 idx = 32 idx/block
    const int idx_per_block = (threads / 32) * IPW;
    const int blocks = (N + idx_per_block - 1) / idx_per_block;

    emb_lookup_kernel<<<blocks, threads>>>(indices, offsets, bucket_keys,
                                           table_offsets, table_bucket_offsets,
                                           num_buckets, emb, out,
                                           N, num_features);
}

// round 7
// speedup vs baseline: 1.4441x; 1.0016x over previous
#include <cuda_runtime.h>
#include <cstdint>

// InferenceEmbeddingTable: hash-bucket lookup + embedding row gather.
// R5: speculative slot prediction with LANE-SPECIALIZED metadata: lanes 0..3
// each own one index (key load, table resolve, bucket hash, predicted slot
// k/nb, 4-byte verification load). Rows broadcast via shfl; 4 speculative
// 512B gathers issued before the verification ballot so L2-check latency
// hides under DRAM-gather latency. Cold fallback = full 128-slot probe.

#define BUCKET_CAP 128
#define IPW 4                      // indices per warp

__global__ __launch_bounds__(256)
void emb_lookup_kernel(const int* __restrict__ indices,
                       const int* __restrict__ offsets,
                       const int* __restrict__ bucket_keys,    // [total_buckets*128]
                       const int* __restrict__ table_offsets,
                       const int* __restrict__ table_bucket_offsets,
                       const int* __restrict__ num_buckets,
                       const float4* __restrict__ emb,         // [total_rows*32]
                       float4* __restrict__ out,               // [N*32]
                       int N, int num_features)
{
    const int gtid = blockIdx.x * blockDim.x + threadIdx.x;
    const int warp = gtid >> 5;
    const int lane = threadIdx.x & 31;
    const int base = warp * IPW;
    if (base >= N) return;

    // ---- lanes 0..3: per-index metadata as scalars -------------------------
    int key = 0, row = 0, bg = 0, gs = 0, tj = 0, bl = 0, chk = 0x80000000;
    bool valid = false;
    if (lane < IPW) {
        const int pos = base + lane;
        key = (pos < N) ? __ldg(&indices[pos]) : 0;
        int t = 0;
        for (int f = 1; f < num_features; ++f)
            t += (pos >= __ldg(&offsets[f]));
        tj = t;
        const unsigned nb = (unsigned)__ldg(&num_buckets[t]);
        unsigned b, g;
        if ((nb & (nb - 1u)) == 0u) {                 // pow2 fast path
            b = (unsigned)key & (nb - 1u);
            g = (unsigned)key >> __popc(nb - 1u);
        } else {
            b = (unsigned)key % nb;
            g = (unsigned)key / nb;
        }
        bl    = (int)b;
        valid = (g < BUCKET_CAP);
        gs    = valid ? (int)g : 0;
        bg    = __ldg(&table_bucket_offsets[t]) + (int)b;
        row   = __ldg(&table_offsets[t]) + (int)b * BUCKET_CAP + gs;
        chk   = __ldg(&bucket_keys[bg * BUCKET_CAP + gs]);   // verification (L2)
    }

    // ---- broadcast rows, launch 4 speculative gathers (DRAM) --------------
    const int r0 = __shfl_sync(0xffffffffu, row, 0);
    const int r1 = __shfl_sync(0xffffffffu, row, 1);
    const int r2 = __shfl_sync(0xffffffffu, row, 2);
    const int r3 = __shfl_sync(0xffffffffu, row, 3);
    const float4 v0 = __ldcs(&emb[r0 * 32 + lane]);
    const float4 v1 = __ldcs(&emb[r1 * 32 + lane]);
    const float4 v2 = __ldcs(&emb[r2 * 32 + lane]);
    const float4 v3 = __ldcs(&emb[r3 * 32 + lane]);

    // ---- verification ballot (chk latency overlapped with gathers) --------
    const unsigned okm = __ballot_sync(0xffffffffu,
                                       (lane < IPW) && valid && (chk == key));

    // ---- commit ------------------------------------------------------------
    if (base + 0 < N) { if (okm & 1u) __stcs(&out[(base + 0) * 32 + lane], v0); }
    if (base + 1 < N) { if (okm & 2u) __stcs(&out[(base + 1) * 32 + lane], v1); }
    if (base + 2 < N) { if (okm & 4u) __stcs(&out[(base + 2) * 32 + lane], v2); }
    if (base + 3 < N) { if (okm & 8u) __stcs(&out[(base + 3) * 32 + lane], v3); }

    // ---- cold fallback: full 128-slot probe for any unverified index ------
    if (__builtin_expect((okm & 0xfu) != 0xfu, 0)) {
        #pragma unroll
        for (int j = 0; j < IPW; ++j) {
            const int pos = base + j;
            if (pos >= N) break;
            if ((okm >> j) & 1u) continue;
            const int kj  = __shfl_sync(0xffffffffu, key, j);
            const int bgj = __shfl_sync(0xffffffffu, bg,  j);
            const int tjj = __shfl_sync(0xffffffffu, tj,  j);
            const int blj = __shfl_sync(0xffffffffu, bl,  j);
            const int4 kk = __ldg((const int4*)bucket_keys + bgj * 32 + lane);
            const int m = (kk.x == kj ? 1 : 0) | (kk.y == kj ? 2 : 0)
                        | (kk.z == kj ? 4 : 0) | (kk.w == kj ? 8 : 0);
            const int cand = m ? (lane * 4 + (__ffs(m) - 1)) : 0x7fffffff;
            const int slot = __reduce_min_sync(0xffffffffu, cand);
            float4 r = make_float4(0.f, 0.f, 0.f, 0.f);
            if (slot < BUCKET_CAP) {
                const int rr = __ldg(&table_offsets[tjj]) + blj * BUCKET_CAP + slot;
                r = __ldcs(&emb[rr * 32 + lane]);
            }
            __stcs(&out[pos * 32 + lane], r);
        }
    }
}

extern "C" void kernel_launch(void* const* d_in, const int* in_sizes, int n_in,
                              void* d_out, int out_size)
{
    const int*    indices              = (const int*)   d_in[0];
    const int*    offsets              = (const int*)   d_in[1];
    const int*    bucket_keys          = (const int*)   d_in[2];
    const int*    table_offsets        = (const int*)   d_in[3];
    const int*    table_bucket_offsets = (const int*)   d_in[4];
    const int*    num_buckets          = (const int*)   d_in[5];
    const float4* emb                  = (const float4*)d_in[6];
    float4*       out                  = (float4*)      d_out;

    const int N            = in_sizes[0];
    const int num_features = in_sizes[5];

    const int threads = 256;                         // 8 warps * 4 idx = 32 idx/block
    const int idx_per_block = (threads / 32) * IPW;
    const int blocks = (N + idx_per_block - 1) / idx_per_block;

    emb_lookup_kernel<<<blocks, threads>>>(indices, offsets, bucket_keys,
                                           table_offsets, table_bucket_offsets,
                                           num_buckets, emb, out,
                                           N, num_features);
}